// round 14
// baseline (speedup 1.0000x reference)
#include <cuda_runtime.h>
#include <cuda_fp16.h>
#include <cstdint>

#define T_TOK   4096
#define D_MODEL 1024
#define E_NUM   8
#define H_DIM   4096
#define P_DIM   256
#define NPAIR   (T_TOK * 2)
#define OUT_MAIN (T_TOK * D_MODEL)
#define CLAMP_MAX 4.605170185988091f

// ---------------- scratch (static device memory; no allocations) ----------------
__device__ __align__(16) float  g_proj[T_TOK * P_DIM];
__device__ __align__(16) __half g_xh[T_TOK * D_MODEL];
__device__ __align__(16) __half g_Ah[(size_t)E_NUM * H_DIM * D_MODEL];
__device__ __align__(16) __half g_Bh[(size_t)E_NUM * D_MODEL * H_DIM];
__device__ __align__(16) __half g_h[(size_t)NPAIR * H_DIM];
__device__ __align__(16) float  g_f[(size_t)NPAIR * D_MODEL];
__device__ __align__(16) float  g_probs[T_TOK * E_NUM];
__device__ int   g_cnt[E_NUM];
__device__ int   g_tok[E_NUM * T_TOK];
__device__ int   g_pairid[E_NUM * T_TOK];
__device__ float g_pw[NPAIR];

// ================= helpers =================
__device__ __forceinline__ uint32_t smem_u32(const void* p) {
    uint32_t a;
    asm("{ .reg .u64 t; cvta.to.shared.u64 t, %1; cvt.u32.u64 %0, t; }" : "=r"(a) : "l"(p));
    return a;
}
#define CP16(sm, gm) \
    asm volatile("{ .reg .u64 gp; cvta.to.global.u64 gp, %1; " \
                 "cp.async.cg.shared.global [%0], [gp], 16; }" \
                 :: "r"(sm), "l"(gm) : "memory")
#define CP_COMMIT()  asm volatile("cp.async.commit_group;" ::: "memory")
#define CP_WAIT(n)   asm volatile("cp.async.wait_group %0;" :: "n"(n) : "memory")

#define LDSM4(r, addr) \
    asm volatile("ldmatrix.sync.aligned.m8n8.x4.shared.b16 {%0,%1,%2,%3}, [%4];" \
        : "=r"((r)[0]), "=r"((r)[1]), "=r"((r)[2]), "=r"((r)[3]) : "r"(addr))

#define MMA_F16(c, a, b0, b1) \
    asm volatile("mma.sync.aligned.m16n8k16.row.col.f32.f16.f16.f32 " \
        "{%0,%1,%2,%3}, {%4,%5,%6,%7}, {%8,%9}, {%0,%1,%2,%3};" \
        : "+f"((c)[0]), "+f"((c)[1]), "+f"((c)[2]), "+f"((c)[3]) \
        : "r"((a)[0]), "r"((a)[1]), "r"((a)[2]), "r"((a)[3]), \
          "r"(b0), "r"(b1))

// ================= fp16 mma.sync grouped NT GEMM =================
// 128x256 CTA tile, 8 warps (2x4) of 64x64 each, BK=32, 3-stage cp.async.
// 1 CTA/SM (regfile-bound); B traffic per C element halved vs 128x128.
// Grid: blockIdx.x = M-tiles (fastest) so consecutive CTAs share one B tile.
#define MBM 128
#define MBN 256
#define ROWB 80                          // bytes per smem row (64 data + 16 pad)
#define A_REG (MBM * ROWB)               // 10240 B
#define STG_B ((MBM + MBN) * ROWB)       // 30720 B per stage
#define SMEM_DYN (3 * STG_B)             // 92160 B

__global__ void __launch_bounds__(256, 1)
hgemm(const __half* __restrict__ Abase, int lda,
      const int* __restrict__ gather,
      const __half* __restrict__ Bbase, size_t bstride,
      const float* __restrict__ biasbase, int biasstride,
      void* __restrict__ Cbase, int ldc,
      const int* __restrict__ crow,
      const int* __restrict__ cntArr, int K, int outHalf)
{
    int z = blockIdx.z;
    int M = cntArr[z];
    int row0 = blockIdx.x * MBM;
    if (row0 >= M) return;
    int col0 = blockIdx.y * MBN;
    const __half* Bexp = Bbase + (size_t)z * bstride;
    const float* bias = biasbase + (size_t)z * biasstride;
    const int* gat = gather + z * T_TOK;
    const int* crs = crow + z * T_TOK;

    __shared__ int arow_s[MBM];
    __shared__ int crow_s[MBM];
    extern __shared__ char ds[];
    uint32_t sbase = smem_u32(ds);

    int tid  = threadIdx.x;          // 256 threads
    int warp = tid >> 5, lane = tid & 31;
    int g = lane >> 2, t = lane & 3;
    int wm = warp >> 2;              // 0..1 : 64-row half
    int wn = warp & 3;               // 0..3 : 64-col quarter of 256

    if (tid < MBM) {
        int r = row0 + tid;
        int rc = min(r, M - 1);
        arow_s[tid] = gat[rc];
        crow_s[tid] = (r < M) ? crs[r] : -1;
    }
    __syncthreads();

    // cp.async slots: each thread fills 2 A rows + 4 B rows (one 16B chunk each)
    int frow = tid >> 2;             // 0..63
    int ch   = tid & 3;              // 16B chunk
    const __half* pa[2];
    const __half* pb[4];
    uint32_t dA[2], dB[4];
#pragma unroll
    for (int r = 0; r < 2; r++) {
        int rowr = frow + r * 64;
        pa[r] = Abase + (size_t)arow_s[rowr] * lda + ch * 8;
        dA[r] = (uint32_t)rowr * ROWB + ch * 16;
    }
#pragma unroll
    for (int r = 0; r < 4; r++) {
        int rowr = frow + r * 64;
        pb[r] = Bexp + (size_t)(col0 + rowr) * K + ch * 8;
        dB[r] = A_REG + (uint32_t)rowr * ROWB + ch * 16;
    }

    // ldmatrix lane offsets
    uint32_t a_off = (uint32_t)((lane & 7) + ((lane >> 3) & 1) * 8) * ROWB + (lane >> 4) * 16;
    uint32_t b_off = (uint32_t)((lane & 7) + ((lane >> 4) & 1) * 8) * ROWB + ((lane >> 3) & 1) * 16;

    int NK = K >> 5;

#pragma unroll
    for (int s = 0; s < 2; s++) {
        uint32_t sb = sbase + s * STG_B;
        int k0 = s * 32;
#pragma unroll
        for (int r = 0; r < 2; r++) CP16(sb + dA[r], pa[r] + k0);
#pragma unroll
        for (int r = 0; r < 4; r++) CP16(sb + dB[r], pb[r] + k0);
        CP_COMMIT();
    }

    float acc[4][8][4];
#pragma unroll
    for (int mi = 0; mi < 4; mi++)
#pragma unroll
        for (int nj = 0; nj < 8; nj++)
#pragma unroll
            for (int q = 0; q < 4; q++) acc[mi][nj][q] = 0.0f;

    int st = 0;
    for (int i = 0; i < NK; i++) {
        if (i + 1 < NK) { CP_WAIT(1); } else { CP_WAIT(0); }
        __syncthreads();

        if (i + 2 < NK) {
            int sn = st + 2; if (sn >= 3) sn -= 3;
            uint32_t sb = sbase + sn * STG_B;
            int k0 = (i + 2) * 32;
#pragma unroll
            for (int r = 0; r < 2; r++) CP16(sb + dA[r], pa[r] + k0);
#pragma unroll
            for (int r = 0; r < 4; r++) CP16(sb + dB[r], pb[r] + k0);
            CP_COMMIT();
        }

        uint32_t stA = sbase + st * STG_B;
        uint32_t stB = stA + A_REG;
#pragma unroll
        for (int kg = 0; kg < 2; kg++) {
            uint32_t af[4][4], bfl[16];
#pragma unroll
            for (int mi = 0; mi < 4; mi++)
                LDSM4(af[mi], stA + (uint32_t)(wm * 64 + mi * 16) * ROWB + kg * 32 + a_off);
#pragma unroll
            for (int j = 0; j < 4; j++)
                LDSM4(&bfl[j * 4], stB + (uint32_t)(wn * 64 + j * 16) * ROWB + kg * 32 + b_off);
#pragma unroll
            for (int mi = 0; mi < 4; mi++)
#pragma unroll
                for (int nj = 0; nj < 8; nj++) {
                    int bi = (nj >> 1) * 4 + (nj & 1) * 2;
                    MMA_F16(acc[mi][nj], af[mi], bfl[bi], bfl[bi + 1]);
                }
        }
        st++; if (st >= 3) st -= 3;
    }

    // epilogue: bias + scattered store
#pragma unroll
    for (int mi = 0; mi < 4; mi++) {
        int rl = wm * 64 + mi * 16 + g;
        int cr0 = crow_s[rl];
        int cr1 = crow_s[rl + 8];
#pragma unroll
        for (int nj = 0; nj < 8; nj++) {
            int cb = col0 + wn * 64 + nj * 8 + 2 * t;
            float2 bv = *reinterpret_cast<const float2*>(bias + cb);
            float ox0 = acc[mi][nj][0] + bv.x, oy0 = acc[mi][nj][1] + bv.y;
            float ox1 = acc[mi][nj][2] + bv.x, oy1 = acc[mi][nj][3] + bv.y;
            if (outHalf) {
                __half* C = (__half*)Cbase;
                if (cr0 >= 0)
                    *reinterpret_cast<__half2*>(C + (size_t)cr0 * ldc + cb) = __floats2half2_rn(ox0, oy0);
                if (cr1 >= 0)
                    *reinterpret_cast<__half2*>(C + (size_t)cr1 * ldc + cb) = __floats2half2_rn(ox1, oy1);
            } else {
                float* C = (float*)Cbase;
                if (cr0 >= 0)
                    *reinterpret_cast<float2*>(C + (size_t)cr0 * ldc + cb) = make_float2(ox0, oy0);
                if (cr1 >= 0)
                    *reinterpret_cast<float2*>(C + (size_t)cr1 * ldc + cb) = make_float2(ox1, oy1);
            }
        }
    }
}

// ---------------- fused f32->f16 conversion for x, A, Bw (one launch) ----------------
#define NX4 (T_TOK * D_MODEL / 4)
#define NA4 ((int)((size_t)E_NUM * H_DIM * D_MODEL / 4))
#define NB4 NA4
#define NCVT_BLOCKS ((NX4 + NA4 + NB4) / 256)

__global__ void cvt_all(const float* __restrict__ x,
                        const float* __restrict__ A,
                        const float* __restrict__ Bw)
{
    int idx = blockIdx.x * 256 + threadIdx.x;
    if (blockIdx.x == 0 && threadIdx.x < E_NUM) g_cnt[threadIdx.x] = 0;

    const float4* src;
    uint2* dst;
    int off;
    if (idx < NX4) {
        src = reinterpret_cast<const float4*>(x);
        dst = reinterpret_cast<uint2*>(g_xh);
        off = idx;
    } else if (idx < NX4 + NA4) {
        src = reinterpret_cast<const float4*>(A);
        dst = reinterpret_cast<uint2*>(g_Ah);
        off = idx - NX4;
    } else {
        src = reinterpret_cast<const float4*>(Bw);
        dst = reinterpret_cast<uint2*>(g_Bh);
        off = idx - NX4 - NA4;
    }
    float4 v = src[off];
    __half2 a = __floats2half2_rn(v.x, v.y);
    __half2 b = __floats2half2_rn(v.z, v.w);
    uint2 u;
    u.x = *reinterpret_cast<uint32_t*>(&a);
    u.y = *reinterpret_cast<uint32_t*>(&b);
    dst[off] = u;
}

// ---------------- fp32 SGEMM (proj only; gating must stay fp32-exact) ----------------
#define BM 64
#define BN 64
#define BK 16

__global__ void __launch_bounds__(128)
sgemm_nt(const float* __restrict__ Abase, int lda,
         const float* __restrict__ B,
         const float* __restrict__ bias,
         float* __restrict__ Cbase, int ldc, int K)
{
    int row0 = blockIdx.y * BM;
    int col0 = blockIdx.x * BN;

    __shared__ float As[BK][68];
    __shared__ float Bs[BK][68];

    int tid = threadIdx.x;
    float acc[8][4];
#pragma unroll
    for (int i = 0; i < 8; i++)
#pragma unroll
        for (int j = 0; j < 4; j++) acc[i][j] = 0.0f;

    int tr = (tid >> 4) * 8;
    int tc = (tid & 15) * 4;

    for (int k0 = 0; k0 < K; k0 += BK) {
#pragma unroll
        for (int l = 0; l < 2; l++) {
            int idx = tid + l * 128;
            int r = idx >> 2;
            int kq = (idx & 3) * 4;
            float4 va = *reinterpret_cast<const float4*>(Abase + (size_t)(row0 + r) * lda + k0 + kq);
            As[kq + 0][r] = va.x; As[kq + 1][r] = va.y; As[kq + 2][r] = va.z; As[kq + 3][r] = va.w;
            float4 vb = *reinterpret_cast<const float4*>(B + (size_t)(col0 + r) * K + k0 + kq);
            Bs[kq + 0][r] = vb.x; Bs[kq + 1][r] = vb.y; Bs[kq + 2][r] = vb.z; Bs[kq + 3][r] = vb.w;
        }
        __syncthreads();
#pragma unroll
        for (int kk = 0; kk < BK; kk++) {
            float4 a0 = *reinterpret_cast<const float4*>(&As[kk][tr]);
            float4 a1 = *reinterpret_cast<const float4*>(&As[kk][tr + 4]);
            float4 b  = *reinterpret_cast<const float4*>(&Bs[kk][tc]);
            float av[8] = {a0.x, a0.y, a0.z, a0.w, a1.x, a1.y, a1.z, a1.w};
            float bv[4] = {b.x, b.y, b.z, b.w};
#pragma unroll
            for (int i = 0; i < 8; i++)
#pragma unroll
                for (int j = 0; j < 4; j++) acc[i][j] += av[i] * bv[j];
        }
        __syncthreads();
    }

    float bvals[4];
#pragma unroll
    for (int j = 0; j < 4; j++) bvals[j] = bias[col0 + tc + j];
#pragma unroll
    for (int i = 0; i < 8; i++) {
        float4 o;
        o.x = acc[i][0] + bvals[0];
        o.y = acc[i][1] + bvals[1];
        o.z = acc[i][2] + bvals[2];
        o.w = acc[i][3] + bvals[3];
        *reinterpret_cast<float4*>(Cbase + (size_t)(row0 + tr + i) * ldc + col0 + tc) = o;
    }
}

// ---------------- gating (computes simn/scale locally) ----------------
__device__ __forceinline__ float warp_sum(float v) {
#pragma unroll
    for (int o = 16; o > 0; o >>= 1) v += __shfl_xor_sync(0xffffffffu, v, o);
    return v;
}

__global__ void gate_kernel(const float* __restrict__ sim, const float* __restrict__ temp) {
    __shared__ float red[E_NUM][P_DIM];
    __shared__ float s_simn[P_DIM * E_NUM];
    int tid = threadIdx.x;  // 256 = P_DIM

    {
        int p = tid;
        float s[E_NUM];
#pragma unroll
        for (int e = 0; e < E_NUM; e++) {
            s[e] = sim[p * E_NUM + e];
            red[e][p] = s[e] * s[e];
        }
        __syncthreads();
        for (int off = 128; off > 0; off >>= 1) {
            if (p < off)
#pragma unroll
                for (int e = 0; e < E_NUM; e++) red[e][p] += red[e][p + off];
            __syncthreads();
        }
#pragma unroll
        for (int e = 0; e < E_NUM; e++) {
            float inv = 1.0f / fmaxf(sqrtf(red[e][0]), 1e-12f);
            s_simn[p * E_NUM + e] = s[e] * inv;
        }
    }
    __syncthreads();
    float scale = expf(fminf(temp[0], CLAMP_MAX));

    int warp = tid >> 5, lane = tid & 31;
    int t = blockIdx.x * 8 + warp;

    float v[8];
#pragma unroll
    for (int j = 0; j < 8; j++) v[j] = g_proj[t * P_DIM + lane + 32 * j];

    float ss = 0.0f;
#pragma unroll
    for (int j = 0; j < 8; j++) ss += v[j] * v[j];
    ss = warp_sum(ss);
    float inv = 1.0f / fmaxf(sqrtf(ss), 1e-12f);

    float l[E_NUM];
#pragma unroll
    for (int e = 0; e < E_NUM; e++) {
        float d = 0.0f;
#pragma unroll
        for (int j = 0; j < 8; j++) d += v[j] * s_simn[(lane + 32 * j) * E_NUM + e];
        l[e] = warp_sum(d);
    }

    if (lane == 0) {
        float m = -1e30f;
#pragma unroll
        for (int e = 0; e < E_NUM; e++) { l[e] = l[e] * inv * scale; m = fmaxf(m, l[e]); }
        float p[E_NUM], s = 0.0f;
#pragma unroll
        for (int e = 0; e < E_NUM; e++) { p[e] = expf(l[e] - m); s += p[e]; }
        float rs = 1.0f / s;
#pragma unroll
        for (int e = 0; e < E_NUM; e++) { p[e] *= rs; g_probs[t * E_NUM + e] = p[e]; }

        float v1 = -1.0f; int i1 = 0;
#pragma unroll
        for (int e = 0; e < E_NUM; e++) if (p[e] > v1) { v1 = p[e]; i1 = e; }
        float v2 = -1.0f; int i2 = 0;
#pragma unroll
        for (int e = 0; e < E_NUM; e++) if (e != i1 && p[e] > v2) { v2 = p[e]; i2 = e; }

        float denom = v1 + v2 + 1e-8f;
        float w1 = v1 / denom, w2 = v2 / denom;

        int s1 = atomicAdd(&g_cnt[i1], 1);
        g_tok[i1 * T_TOK + s1]    = t;
        g_pairid[i1 * T_TOK + s1] = 2 * t;
        g_pw[2 * t] = w1;
        int s2 = atomicAdd(&g_cnt[i2], 1);
        g_tok[i2 * T_TOK + s2]    = t;
        g_pairid[i2 * T_TOK + s2] = 2 * t + 1;
        g_pw[2 * t + 1] = w2;
    }
}

// ---------------- combine ----------------
__global__ void combine_kernel(const float* __restrict__ x, float* __restrict__ out) {
    int idx = blockIdx.x * 256 + threadIdx.x;
    int t  = idx >> 8;
    int c4 = idx & 255;
    float w0 = g_pw[2 * t], w1 = g_pw[2 * t + 1];
    float ws = w0 + w1;
    const float4* x4 = reinterpret_cast<const float4*>(x);
    const float4* f4 = reinterpret_cast<const float4*>(g_f);
    float4 xv = x4[idx];
    float4 f0 = f4[(size_t)(2 * t) * 256 + c4];
    float4 f1 = f4[(size_t)(2 * t + 1) * 256 + c4];
    float4 o;
    o.x = ws * xv.x + w0 * f0.x + w1 * f1.x;
    o.y = ws * xv.y + w0 * f0.y + w1 * f1.y;
    o.z = ws * xv.z + w0 * f0.z + w1 * f1.z;
    o.w = ws * xv.w + w0 * f0.w + w1 * f1.w;
    reinterpret_cast<float4*>(out)[idx] = o;
}

// ---------------- finalize (1024 threads; same per-expert reduction order) ----------------
__global__ void finalize_kernel(float* __restrict__ out) {
    __shared__ float red[1024];
    __shared__ float fr[E_NUM];
    int tid = threadIdx.x;  // 1024
    float part[E_NUM];
#pragma unroll
    for (int e = 0; e < E_NUM; e++) part[e] = 0.0f;
    for (int t = tid; t < T_TOK; t += 1024)
#pragma unroll
        for (int e = 0; e < E_NUM; e++) part[e] += g_probs[t * E_NUM + e];

    for (int e = 0; e < E_NUM; e++) {
        red[tid] = part[e];
        __syncthreads();
        for (int off = 512; off > 0; off >>= 1) {
            if (tid < off) red[tid] += red[tid + off];
            __syncthreads();
        }
        if (tid == 0) fr[e] = red[0] / (float)T_TOK;
        __syncthreads();
    }
    if (tid == 0) {
        float aux = 0.0f;
#pragma unroll
        for (int e = 0; e < E_NUM; e++) {
            float d = fr[e] - 1.0f / (float)E_NUM;
            aux += d * d;
        }
        out[OUT_MAIN] = aux;
#pragma unroll
        for (int e = 0; e < E_NUM; e++) out[OUT_MAIN + 1 + e] = fr[e];
#pragma unroll
        for (int e = 0; e < E_NUM; e++) out[OUT_MAIN + 9 + e] = (float)g_cnt[e];
    }
}

// ---------------- launch (strict serial) ----------------
extern "C" void kernel_launch(void* const* d_in, const int* in_sizes, int n_in,
                              void* d_out, int out_size) {
    const float* x    = (const float*)d_in[0];
    const float* Wp   = (const float*)d_in[1];
    const float* bp   = (const float*)d_in[2];
    const float* sim  = (const float*)d_in[3];
    const float* temp = (const float*)d_in[4];
    const float* A    = (const float*)d_in[5];
    const float* ab   = (const float*)d_in[6];
    const float* Bw   = (const float*)d_in[7];
    const float* bb   = (const float*)d_in[8];
    float* out = (float*)d_out;

    float *p_proj, *p_f;
    __half *p_xh, *p_Ah, *p_Bh, *p_h;
    int *p_tok, *p_pair, *p_cnt;
    cudaGetSymbolAddress((void**)&p_proj, g_proj);
    cudaGetSymbolAddress((void**)&p_xh,   g_xh);
    cudaGetSymbolAddress((void**)&p_Ah,   g_Ah);
    cudaGetSymbolAddress((void**)&p_Bh,   g_Bh);
    cudaGetSymbolAddress((void**)&p_h,    g_h);
    cudaGetSymbolAddress((void**)&p_f,    g_f);
    cudaGetSymbolAddress((void**)&p_tok,  g_tok);
    cudaGetSymbolAddress((void**)&p_pair, g_pairid);
    cudaGetSymbolAddress((void**)&p_cnt,  g_cnt);

    cudaFuncSetAttribute(hgemm, cudaFuncAttributeMaxDynamicSharedMemorySize, SMEM_DYN);

    // 0) fused fp16 conversions (x, A, Bw) + counter zeroing — one launch
    cvt_all<<<NCVT_BLOCKS, 256>>>(x, A, Bw);

    // 1) proj = X @ Wp^T + bp  (fp32 exact — gating is decision-sensitive)
    sgemm_nt<<<dim3(P_DIM / BN, T_TOK / BM, 1), 128>>>(
        x, D_MODEL, Wp, bp, p_proj, P_DIM, D_MODEL);

    // 2) gating + routing
    gate_kernel<<<T_TOK / 8, 256>>>(sim, temp);

    // 3) h = gather(xh) @ Ah_e^T + a_bias   (fp16 mma, fp16 out)
    hgemm<<<dim3(T_TOK / MBM, H_DIM / MBN, E_NUM), 256, SMEM_DYN>>>(
        p_xh, D_MODEL, p_tok,
        p_Ah, (size_t)H_DIM * D_MODEL, ab, H_DIM,
        p_h, H_DIM, p_pair,
        p_cnt, D_MODEL, 1);

    // 4) f = gather(h) @ Bh_e^T + b_bias    (fp16 mma, fp32 out)
    hgemm<<<dim3(T_TOK / MBM, D_MODEL / MBN, E_NUM), 256, SMEM_DYN>>>(
        p_h, H_DIM, p_pair,
        p_Bh, (size_t)D_MODEL * H_DIM, bb, D_MODEL,
        p_f, D_MODEL, p_pair,
        p_cnt, H_DIM, 0);

    // 5) combine
    combine_kernel<<<(T_TOK * D_MODEL / 4) / 256, 256>>>(x, out);

    // 6) aux outputs
    finalize_kernel<<<1, 1024>>>(out);
}

// round 15
// speedup vs baseline: 1.2276x; 1.2276x over previous
#include <cuda_runtime.h>
#include <cuda_fp16.h>
#include <cstdint>

#define T_TOK   4096
#define D_MODEL 1024
#define E_NUM   8
#define H_DIM   4096
#define P_DIM   256
#define NPAIR   (T_TOK * 2)
#define OUT_MAIN (T_TOK * D_MODEL)
#define CLAMP_MAX 4.605170185988091f

// ---------------- scratch (static device memory; no allocations) ----------------
__device__ __align__(16) float  g_proj[T_TOK * P_DIM];
__device__ __align__(16) __half g_xh[T_TOK * D_MODEL];
__device__ __align__(16) __half g_Ah[(size_t)E_NUM * H_DIM * D_MODEL];
__device__ __align__(16) __half g_Bh[(size_t)E_NUM * D_MODEL * H_DIM];
__device__ __align__(16) __half g_h[(size_t)NPAIR * H_DIM];
__device__ __align__(16) float  g_probs[T_TOK * E_NUM];
__device__ int   g_cnt[E_NUM];
__device__ int   g_tok[E_NUM * T_TOK];
__device__ int   g_pairid[E_NUM * T_TOK];
__device__ float g_pw[NPAIR];

// ================= helpers =================
__device__ __forceinline__ uint32_t smem_u32(const void* p) {
    uint32_t a;
    asm("{ .reg .u64 t; cvta.to.shared.u64 t, %1; cvt.u32.u64 %0, t; }" : "=r"(a) : "l"(p));
    return a;
}
#define CP16(sm, gm) \
    asm volatile("{ .reg .u64 gp; cvta.to.global.u64 gp, %1; " \
                 "cp.async.cg.shared.global [%0], [gp], 16; }" \
                 :: "r"(sm), "l"(gm) : "memory")
#define CP_COMMIT()  asm volatile("cp.async.commit_group;" ::: "memory")
#define CP_WAIT(n)   asm volatile("cp.async.wait_group %0;" :: "n"(n) : "memory")

#define LDSM4(r, addr) \
    asm volatile("ldmatrix.sync.aligned.m8n8.x4.shared.b16 {%0,%1,%2,%3}, [%4];" \
        : "=r"((r)[0]), "=r"((r)[1]), "=r"((r)[2]), "=r"((r)[3]) : "r"(addr))

#define MMA_F16(c, a, b0, b1) \
    asm volatile("mma.sync.aligned.m16n8k16.row.col.f32.f16.f16.f32 " \
        "{%0,%1,%2,%3}, {%4,%5,%6,%7}, {%8,%9}, {%0,%1,%2,%3};" \
        : "+f"((c)[0]), "+f"((c)[1]), "+f"((c)[2]), "+f"((c)[3]) \
        : "r"((a)[0]), "r"((a)[1]), "r"((a)[2]), "r"((a)[3]), \
          "r"(b0), "r"(b1))

// ================= fp16 mma.sync grouped NT GEMM =================
// 128x128 CTA tile, 4 warps (2x2) of 64x64 each, BK=32, 3-stage cp.async.
// Grid: blockIdx.x = M-tiles (fastest) so consecutive CTAs share one B tile.
// outMode: 1 = fp16 scatter store (h); 2 = weighted atomic accumulate into out (f).
#define MBM 128
#define MBN 128
#define ROWB 80
#define A_REG (MBM * ROWB)
#define STG_B (2 * A_REG)
#define SMEM_DYN (3 * STG_B)

__global__ void __launch_bounds__(128, 2)
hgemm(const __half* __restrict__ Abase, int lda,
      const int* __restrict__ gather,
      const __half* __restrict__ Bbase, size_t bstride,
      const float* __restrict__ biasbase, int biasstride,
      void* __restrict__ Cbase, int ldc,
      const int* __restrict__ crow,
      const int* __restrict__ cntArr, int K, int outMode)
{
    int z = blockIdx.z;
    int M = cntArr[z];
    int row0 = blockIdx.x * MBM;
    if (row0 >= M) return;
    int col0 = blockIdx.y * MBN;
    const __half* Bexp = Bbase + (size_t)z * bstride;
    const float* bias = biasbase + (size_t)z * biasstride;
    const int* gat = gather + z * T_TOK;
    const int* crs = crow + z * T_TOK;

    __shared__ int arow_s[MBM];
    __shared__ int crow_s[MBM];
    extern __shared__ char ds[];
    uint32_t sbase = smem_u32(ds);

    int tid  = threadIdx.x;
    int warp = tid >> 5, lane = tid & 31;
    int g = lane >> 2, t = lane & 3;
    int wm = warp >> 1;
    int wn = warp & 1;

    {
        int r = row0 + tid;
        int rc = min(r, M - 1);
        arow_s[tid] = gat[rc];
        crow_s[tid] = (r < M) ? crs[r] : -1;
    }
    __syncthreads();

    int frow = tid >> 2;
    int ch   = tid & 3;
    const __half* pa[4];
    const __half* pb[4];
    uint32_t dA[4], dB[4];
#pragma unroll
    for (int r = 0; r < 4; r++) {
        int rowr = frow + r * 32;
        pa[r] = Abase + (size_t)arow_s[rowr] * lda + ch * 8;
        pb[r] = Bexp + (size_t)(col0 + rowr) * K + ch * 8;
        dA[r] = (uint32_t)rowr * ROWB + ch * 16;
        dB[r] = dA[r] + A_REG;
    }

    uint32_t a_off = (uint32_t)((lane & 7) + ((lane >> 3) & 1) * 8) * ROWB + (lane >> 4) * 16;
    uint32_t b_off = (uint32_t)((lane & 7) + ((lane >> 4) & 1) * 8) * ROWB + ((lane >> 3) & 1) * 16;

    int NK = K >> 5;

#pragma unroll
    for (int s = 0; s < 2; s++) {
        uint32_t sb = sbase + s * STG_B;
        int k0 = s * 32;
#pragma unroll
        for (int r = 0; r < 4; r++) {
            CP16(sb + dA[r], pa[r] + k0);
            CP16(sb + dB[r], pb[r] + k0);
        }
        CP_COMMIT();
    }

    float acc[4][8][4];
#pragma unroll
    for (int mi = 0; mi < 4; mi++)
#pragma unroll
        for (int nj = 0; nj < 8; nj++)
#pragma unroll
            for (int q = 0; q < 4; q++) acc[mi][nj][q] = 0.0f;

    int st = 0;
    for (int i = 0; i < NK; i++) {
        if (i + 1 < NK) { CP_WAIT(1); } else { CP_WAIT(0); }
        __syncthreads();

        if (i + 2 < NK) {
            int sn = st + 2; if (sn >= 3) sn -= 3;
            uint32_t sb = sbase + sn * STG_B;
            int k0 = (i + 2) * 32;
#pragma unroll
            for (int r = 0; r < 4; r++) {
                CP16(sb + dA[r], pa[r] + k0);
                CP16(sb + dB[r], pb[r] + k0);
            }
            CP_COMMIT();
        }

        uint32_t stA = sbase + st * STG_B;
        uint32_t stB = stA + A_REG;
#pragma unroll
        for (int kg = 0; kg < 2; kg++) {
            uint32_t af[4][4], bfl[16];
#pragma unroll
            for (int mi = 0; mi < 4; mi++)
                LDSM4(af[mi], stA + (uint32_t)(wm * 64 + mi * 16) * ROWB + kg * 32 + a_off);
#pragma unroll
            for (int j = 0; j < 4; j++)
                LDSM4(&bfl[j * 4], stB + (uint32_t)(wn * 64 + j * 16) * ROWB + kg * 32 + b_off);
#pragma unroll
            for (int mi = 0; mi < 4; mi++)
#pragma unroll
                for (int nj = 0; nj < 8; nj++) {
                    int bi = (nj >> 1) * 4 + (nj & 1) * 2;
                    MMA_F16(acc[mi][nj], af[mi], bfl[bi], bfl[bi + 1]);
                }
        }
        st++; if (st >= 3) st -= 3;
    }

    // epilogue
#pragma unroll
    for (int mi = 0; mi < 4; mi++) {
        int rl = wm * 64 + mi * 16 + g;
        int cr0 = crow_s[rl];
        int cr1 = crow_s[rl + 8];
        float w0 = 0.0f, w1 = 0.0f;
        if (outMode == 2) {
            if (cr0 >= 0) w0 = g_pw[cr0];
            if (cr1 >= 0) w1 = g_pw[cr1];
        }
#pragma unroll
        for (int nj = 0; nj < 8; nj++) {
            int cb = col0 + wn * 64 + nj * 8 + 2 * t;
            float2 bv = *reinterpret_cast<const float2*>(bias + cb);
            float ox0 = acc[mi][nj][0] + bv.x, oy0 = acc[mi][nj][1] + bv.y;
            float ox1 = acc[mi][nj][2] + bv.x, oy1 = acc[mi][nj][3] + bv.y;
            if (outMode == 1) {
                __half* C = (__half*)Cbase;
                if (cr0 >= 0)
                    *reinterpret_cast<__half2*>(C + (size_t)cr0 * ldc + cb) = __floats2half2_rn(ox0, oy0);
                if (cr1 >= 0)
                    *reinterpret_cast<__half2*>(C + (size_t)cr1 * ldc + cb) = __floats2half2_rn(ox1, oy1);
            } else {
                float* C = (float*)Cbase;
                if (cr0 >= 0) {
                    float* dst = C + (size_t)(cr0 >> 1) * ldc + cb;
                    atomicAdd(dst,     w0 * ox0);
                    atomicAdd(dst + 1, w0 * oy0);
                }
                if (cr1 >= 0) {
                    float* dst = C + (size_t)(cr1 >> 1) * ldc + cb;
                    atomicAdd(dst,     w1 * ox1);
                    atomicAdd(dst + 1, w1 * oy1);
                }
            }
        }
    }
}

// ---------------- fused f32->f16 conversion for x, A, Bw (one launch) ----------------
#define NX4 (T_TOK * D_MODEL / 4)
#define NA4 ((int)((size_t)E_NUM * H_DIM * D_MODEL / 4))
#define NB4 NA4
#define NCVT_BLOCKS ((NX4 + NA4 + NB4) / 256)

__global__ void cvt_all(const float* __restrict__ x,
                        const float* __restrict__ A,
                        const float* __restrict__ Bw)
{
    int idx = blockIdx.x * 256 + threadIdx.x;
    if (blockIdx.x == 0 && threadIdx.x < E_NUM) g_cnt[threadIdx.x] = 0;

    const float4* src;
    uint2* dst;
    int off;
    if (idx < NX4) {
        src = reinterpret_cast<const float4*>(x);
        dst = reinterpret_cast<uint2*>(g_xh);
        off = idx;
    } else if (idx < NX4 + NA4) {
        src = reinterpret_cast<const float4*>(A);
        dst = reinterpret_cast<uint2*>(g_Ah);
        off = idx - NX4;
    } else {
        src = reinterpret_cast<const float4*>(Bw);
        dst = reinterpret_cast<uint2*>(g_Bh);
        off = idx - NX4 - NA4;
    }
    float4 v = src[off];
    __half2 a = __floats2half2_rn(v.x, v.y);
    __half2 b = __floats2half2_rn(v.z, v.w);
    uint2 u;
    u.x = *reinterpret_cast<uint32_t*>(&a);
    u.y = *reinterpret_cast<uint32_t*>(&b);
    dst[off] = u;
}

// ---------------- fp32 SGEMM (proj only; gating must stay fp32-exact) ----------------
#define BM 64
#define BN 64
#define BK 16

__global__ void __launch_bounds__(128)
sgemm_nt(const float* __restrict__ Abase, int lda,
         const float* __restrict__ B,
         const float* __restrict__ bias,
         float* __restrict__ Cbase, int ldc, int K)
{
    int row0 = blockIdx.y * BM;
    int col0 = blockIdx.x * BN;

    __shared__ float As[BK][68];
    __shared__ float Bs[BK][68];

    int tid = threadIdx.x;
    float acc[8][4];
#pragma unroll
    for (int i = 0; i < 8; i++)
#pragma unroll
        for (int j = 0; j < 4; j++) acc[i][j] = 0.0f;

    int tr = (tid >> 4) * 8;
    int tc = (tid & 15) * 4;

    for (int k0 = 0; k0 < K; k0 += BK) {
#pragma unroll
        for (int l = 0; l < 2; l++) {
            int idx = tid + l * 128;
            int r = idx >> 2;
            int kq = (idx & 3) * 4;
            float4 va = *reinterpret_cast<const float4*>(Abase + (size_t)(row0 + r) * lda + k0 + kq);
            As[kq + 0][r] = va.x; As[kq + 1][r] = va.y; As[kq + 2][r] = va.z; As[kq + 3][r] = va.w;
            float4 vb = *reinterpret_cast<const float4*>(B + (size_t)(col0 + r) * K + k0 + kq);
            Bs[kq + 0][r] = vb.x; Bs[kq + 1][r] = vb.y; Bs[kq + 2][r] = vb.z; Bs[kq + 3][r] = vb.w;
        }
        __syncthreads();
#pragma unroll
        for (int kk = 0; kk < BK; kk++) {
            float4 a0 = *reinterpret_cast<const float4*>(&As[kk][tr]);
            float4 a1 = *reinterpret_cast<const float4*>(&As[kk][tr + 4]);
            float4 b  = *reinterpret_cast<const float4*>(&Bs[kk][tc]);
            float av[8] = {a0.x, a0.y, a0.z, a0.w, a1.x, a1.y, a1.z, a1.w};
            float bv[4] = {b.x, b.y, b.z, b.w};
#pragma unroll
            for (int i = 0; i < 8; i++)
#pragma unroll
                for (int j = 0; j < 4; j++) acc[i][j] += av[i] * bv[j];
        }
        __syncthreads();
    }

    float bvals[4];
#pragma unroll
    for (int j = 0; j < 4; j++) bvals[j] = bias[col0 + tc + j];
#pragma unroll
    for (int i = 0; i < 8; i++) {
        float4 o;
        o.x = acc[i][0] + bvals[0];
        o.y = acc[i][1] + bvals[1];
        o.z = acc[i][2] + bvals[2];
        o.w = acc[i][3] + bvals[3];
        *reinterpret_cast<float4*>(Cbase + (size_t)(row0 + tr + i) * ldc + col0 + tc) = o;
    }
}

// ---------------- gating (computes simn/scale locally) ----------------
__device__ __forceinline__ float warp_sum(float v) {
#pragma unroll
    for (int o = 16; o > 0; o >>= 1) v += __shfl_xor_sync(0xffffffffu, v, o);
    return v;
}

__global__ void gate_kernel(const float* __restrict__ sim, const float* __restrict__ temp) {
    __shared__ float red[E_NUM][P_DIM];
    __shared__ float s_simn[P_DIM * E_NUM];
    int tid = threadIdx.x;  // 256 = P_DIM

    {
        int p = tid;
        float s[E_NUM];
#pragma unroll
        for (int e = 0; e < E_NUM; e++) {
            s[e] = sim[p * E_NUM + e];
            red[e][p] = s[e] * s[e];
        }
        __syncthreads();
        for (int off = 128; off > 0; off >>= 1) {
            if (p < off)
#pragma unroll
                for (int e = 0; e < E_NUM; e++) red[e][p] += red[e][p + off];
            __syncthreads();
        }
#pragma unroll
        for (int e = 0; e < E_NUM; e++) {
            float inv = 1.0f / fmaxf(sqrtf(red[e][0]), 1e-12f);
            s_simn[p * E_NUM + e] = s[e] * inv;
        }
    }
    __syncthreads();
    float scale = expf(fminf(temp[0], CLAMP_MAX));

    int warp = tid >> 5, lane = tid & 31;
    int t = blockIdx.x * 8 + warp;

    float v[8];
#pragma unroll
    for (int j = 0; j < 8; j++) v[j] = g_proj[t * P_DIM + lane + 32 * j];

    float ss = 0.0f;
#pragma unroll
    for (int j = 0; j < 8; j++) ss += v[j] * v[j];
    ss = warp_sum(ss);
    float inv = 1.0f / fmaxf(sqrtf(ss), 1e-12f);

    float l[E_NUM];
#pragma unroll
    for (int e = 0; e < E_NUM; e++) {
        float d = 0.0f;
#pragma unroll
        for (int j = 0; j < 8; j++) d += v[j] * s_simn[(lane + 32 * j) * E_NUM + e];
        l[e] = warp_sum(d);
    }

    if (lane == 0) {
        float m = -1e30f;
#pragma unroll
        for (int e = 0; e < E_NUM; e++) { l[e] = l[e] * inv * scale; m = fmaxf(m, l[e]); }
        float p[E_NUM], s = 0.0f;
#pragma unroll
        for (int e = 0; e < E_NUM; e++) { p[e] = expf(l[e] - m); s += p[e]; }
        float rs = 1.0f / s;
#pragma unroll
        for (int e = 0; e < E_NUM; e++) { p[e] *= rs; g_probs[t * E_NUM + e] = p[e]; }

        float v1 = -1.0f; int i1 = 0;
#pragma unroll
        for (int e = 0; e < E_NUM; e++) if (p[e] > v1) { v1 = p[e]; i1 = e; }
        float v2 = -1.0f; int i2 = 0;
#pragma unroll
        for (int e = 0; e < E_NUM; e++) if (e != i1 && p[e] > v2) { v2 = p[e]; i2 = e; }

        float denom = v1 + v2 + 1e-8f;
        float w1 = v1 / denom, w2 = v2 / denom;

        int s1 = atomicAdd(&g_cnt[i1], 1);
        g_tok[i1 * T_TOK + s1]    = t;
        g_pairid[i1 * T_TOK + s1] = 2 * t;
        g_pw[2 * t] = w1;
        int s2 = atomicAdd(&g_cnt[i2], 1);
        g_tok[i2 * T_TOK + s2]    = t;
        g_pairid[i2 * T_TOK + s2] = 2 * t + 1;
        g_pw[2 * t + 1] = w2;
    }
}

// ---------------- xw: out = (w0+w1)*x (base for f-gemm atomic accumulation) ----------------
__global__ void xw_kernel(const float* __restrict__ x, float* __restrict__ out) {
    int idx = blockIdx.x * 256 + threadIdx.x;
    int t = idx >> 8;
    float ws = g_pw[2 * t] + g_pw[2 * t + 1];
    float4 xv = reinterpret_cast<const float4*>(x)[idx];
    float4 o;
    o.x = ws * xv.x; o.y = ws * xv.y; o.z = ws * xv.z; o.w = ws * xv.w;
    reinterpret_cast<float4*>(out)[idx] = o;
}

// ---------------- finalize (1024 threads; same per-expert reduction order) ----------------
__global__ void finalize_kernel(float* __restrict__ out) {
    __shared__ float red[1024];
    __shared__ float fr[E_NUM];
    int tid = threadIdx.x;  // 1024
    float part[E_NUM];
#pragma unroll
    for (int e = 0; e < E_NUM; e++) part[e] = 0.0f;
    for (int t = tid; t < T_TOK; t += 1024)
#pragma unroll
        for (int e = 0; e < E_NUM; e++) part[e] += g_probs[t * E_NUM + e];

    for (int e = 0; e < E_NUM; e++) {
        red[tid] = part[e];
        __syncthreads();
        for (int off = 512; off > 0; off >>= 1) {
            if (tid < off) red[tid] += red[tid + off];
            __syncthreads();
        }
        if (tid == 0) fr[e] = red[0] / (float)T_TOK;
        __syncthreads();
    }
    if (tid == 0) {
        float aux = 0.0f;
#pragma unroll
        for (int e = 0; e < E_NUM; e++) {
            float d = fr[e] - 1.0f / (float)E_NUM;
            aux += d * d;
        }
        out[OUT_MAIN] = aux;
#pragma unroll
        for (int e = 0; e < E_NUM; e++) out[OUT_MAIN + 1 + e] = fr[e];
#pragma unroll
        for (int e = 0; e < E_NUM; e++) out[OUT_MAIN + 9 + e] = (float)g_cnt[e];
    }
}

// ---------------- launch (strict serial) ----------------
extern "C" void kernel_launch(void* const* d_in, const int* in_sizes, int n_in,
                              void* d_out, int out_size) {
    const float* x    = (const float*)d_in[0];
    const float* Wp   = (const float*)d_in[1];
    const float* bp   = (const float*)d_in[2];
    const float* sim  = (const float*)d_in[3];
    const float* temp = (const float*)d_in[4];
    const float* A    = (const float*)d_in[5];
    const float* ab   = (const float*)d_in[6];
    const float* Bw   = (const float*)d_in[7];
    const float* bb   = (const float*)d_in[8];
    float* out = (float*)d_out;

    float *p_proj;
    __half *p_xh, *p_Ah, *p_Bh, *p_h;
    int *p_tok, *p_pair, *p_cnt;
    cudaGetSymbolAddress((void**)&p_proj, g_proj);
    cudaGetSymbolAddress((void**)&p_xh,   g_xh);
    cudaGetSymbolAddress((void**)&p_Ah,   g_Ah);
    cudaGetSymbolAddress((void**)&p_Bh,   g_Bh);
    cudaGetSymbolAddress((void**)&p_h,    g_h);
    cudaGetSymbolAddress((void**)&p_tok,  g_tok);
    cudaGetSymbolAddress((void**)&p_pair, g_pairid);
    cudaGetSymbolAddress((void**)&p_cnt,  g_cnt);

    cudaFuncSetAttribute(hgemm, cudaFuncAttributeMaxDynamicSharedMemorySize, SMEM_DYN);

    // 0) fused fp16 conversions (x, A, Bw) + counter zeroing — one launch
    cvt_all<<<NCVT_BLOCKS, 256>>>(x, A, Bw);

    // 1) proj = X @ Wp^T + bp  (fp32 exact — gating is decision-sensitive)
    sgemm_nt<<<dim3(P_DIM / BN, T_TOK / BM, 1), 128>>>(
        x, D_MODEL, Wp, bp, p_proj, P_DIM, D_MODEL);

    // 2) gating + routing
    gate_kernel<<<T_TOK / 8, 256>>>(sim, temp);

    // 3) h = gather(xh) @ Ah_e^T + a_bias   (fp16 mma, fp16 out)
    hgemm<<<dim3(T_TOK / MBM, H_DIM / MBN, E_NUM), 128, SMEM_DYN>>>(
        p_xh, D_MODEL, p_tok,
        p_Ah, (size_t)H_DIM * D_MODEL, ab, H_DIM,
        p_h, H_DIM, p_pair,
        p_cnt, D_MODEL, 1);

    // 4) out = (w0+w1)*x (base value; f-gemm accumulates on top)
    xw_kernel<<<(T_TOK * D_MODEL / 4) / 256, 256>>>(x, out);

    // 5) f-gemm: atomically accumulates w * (gather(h) @ Bh_e^T + b_bias) into out
    hgemm<<<dim3(T_TOK / MBM, D_MODEL / MBN, E_NUM), 128, SMEM_DYN>>>(
        p_h, H_DIM, p_pair,
        p_Bh, (size_t)D_MODEL * H_DIM, bb, D_MODEL,
        out, D_MODEL, p_pair,
        p_cnt, H_DIM, 2);

    // 6) aux outputs
    finalize_kernel<<<1, 1024>>>(out);
}

// round 16
// speedup vs baseline: 1.2410x; 1.0110x over previous
#include <cuda_runtime.h>
#include <cuda_fp16.h>
#include <cstdint>

#define T_TOK   4096
#define D_MODEL 1024
#define E_NUM   8
#define H_DIM   4096
#define P_DIM   256
#define NPAIR   (T_TOK * 2)
#define OUT_MAIN (T_TOK * D_MODEL)
#define CLAMP_MAX 4.605170185988091f

// ---------------- scratch (static device memory; no allocations) ----------------
__device__ __align__(16) float  g_proj[T_TOK * P_DIM];
__device__ __align__(16) __half g_xh[T_TOK * D_MODEL];
__device__ __align__(16) __half g_Ah[(size_t)E_NUM * H_DIM * D_MODEL];
__device__ __align__(16) __half g_Bh[(size_t)E_NUM * D_MODEL * H_DIM];
__device__ __align__(16) __half g_h[(size_t)NPAIR * H_DIM];
__device__ __align__(16) float  g_f[(size_t)NPAIR * D_MODEL];
__device__ __align__(16) float  g_probs[T_TOK * E_NUM];
__device__ int   g_cnt[E_NUM];
__device__ int   g_tok[E_NUM * T_TOK];
__device__ int   g_pairid[E_NUM * T_TOK];
__device__ float g_pw[NPAIR];

// ================= helpers =================
__device__ __forceinline__ uint32_t smem_u32(const void* p) {
    uint32_t a;
    asm("{ .reg .u64 t; cvta.to.shared.u64 t, %1; cvt.u32.u64 %0, t; }" : "=r"(a) : "l"(p));
    return a;
}
#define CP16(sm, gm) \
    asm volatile("{ .reg .u64 gp; cvta.to.global.u64 gp, %1; " \
                 "cp.async.cg.shared.global [%0], [gp], 16; }" \
                 :: "r"(sm), "l"(gm) : "memory")
#define CP_COMMIT()  asm volatile("cp.async.commit_group;" ::: "memory")
#define CP_WAIT(n)   asm volatile("cp.async.wait_group %0;" :: "n"(n) : "memory")

#define LDSM4(r, addr) \
    asm volatile("ldmatrix.sync.aligned.m8n8.x4.shared.b16 {%0,%1,%2,%3}, [%4];" \
        : "=r"((r)[0]), "=r"((r)[1]), "=r"((r)[2]), "=r"((r)[3]) : "r"(addr))

#define MMA_F16(c, a, b0, b1) \
    asm volatile("mma.sync.aligned.m16n8k16.row.col.f32.f16.f16.f32 " \
        "{%0,%1,%2,%3}, {%4,%5,%6,%7}, {%8,%9}, {%0,%1,%2,%3};" \
        : "+f"((c)[0]), "+f"((c)[1]), "+f"((c)[2]), "+f"((c)[3]) \
        : "r"((a)[0]), "r"((a)[1]), "r"((a)[2]), "r"((a)[3]), \
          "r"(b0), "r"(b1))

// ================= fp16 mma.sync grouped NT GEMM (R11 config — final) =================
#define MBM 128
#define MBN 128
#define ROWB 80
#define A_REG (MBM * ROWB)
#define STG_B (2 * A_REG)
#define SMEM_DYN (3 * STG_B)

__global__ void __launch_bounds__(128, 2)
hgemm(const __half* __restrict__ Abase, int lda,
      const int* __restrict__ gather,
      const __half* __restrict__ Bbase, size_t bstride,
      const float* __restrict__ biasbase, int biasstride,
      void* __restrict__ Cbase, int ldc,
      const int* __restrict__ crow,
      const int* __restrict__ cntArr, int K, int outHalf)
{
    int z = blockIdx.z;
    int M = cntArr[z];
    int row0 = blockIdx.x * MBM;
    if (row0 >= M) return;
    int col0 = blockIdx.y * MBN;
    const __half* Bexp = Bbase + (size_t)z * bstride;
    const float* bias = biasbase + (size_t)z * biasstride;
    const int* gat = gather + z * T_TOK;
    const int* crs = crow + z * T_TOK;

    __shared__ int arow_s[MBM];
    __shared__ int crow_s[MBM];
    extern __shared__ char ds[];
    uint32_t sbase = smem_u32(ds);

    int tid  = threadIdx.x;
    int warp = tid >> 5, lane = tid & 31;
    int g = lane >> 2, t = lane & 3;
    int wm = warp >> 1;
    int wn = warp & 1;

    {
        int r = row0 + tid;
        int rc = min(r, M - 1);
        arow_s[tid] = gat[rc];
        crow_s[tid] = (r < M) ? crs[r] : -1;
    }
    __syncthreads();

    int frow = tid >> 2;
    int ch   = tid & 3;
    const __half* pa[4];
    const __half* pb[4];
    uint32_t dA[4], dB[4];
#pragma unroll
    for (int r = 0; r < 4; r++) {
        int rowr = frow + r * 32;
        pa[r] = Abase + (size_t)arow_s[rowr] * lda + ch * 8;
        pb[r] = Bexp + (size_t)(col0 + rowr) * K + ch * 8;
        dA[r] = (uint32_t)rowr * ROWB + ch * 16;
        dB[r] = dA[r] + A_REG;
    }

    uint32_t a_off = (uint32_t)((lane & 7) + ((lane >> 3) & 1) * 8) * ROWB + (lane >> 4) * 16;
    uint32_t b_off = (uint32_t)((lane & 7) + ((lane >> 4) & 1) * 8) * ROWB + ((lane >> 3) & 1) * 16;

    int NK = K >> 5;

#pragma unroll
    for (int s = 0; s < 2; s++) {
        uint32_t sb = sbase + s * STG_B;
        int k0 = s * 32;
#pragma unroll
        for (int r = 0; r < 4; r++) {
            CP16(sb + dA[r], pa[r] + k0);
            CP16(sb + dB[r], pb[r] + k0);
        }
        CP_COMMIT();
    }

    float acc[4][8][4];
#pragma unroll
    for (int mi = 0; mi < 4; mi++)
#pragma unroll
        for (int nj = 0; nj < 8; nj++)
#pragma unroll
            for (int q = 0; q < 4; q++) acc[mi][nj][q] = 0.0f;

    int st = 0;
    for (int i = 0; i < NK; i++) {
        if (i + 1 < NK) { CP_WAIT(1); } else { CP_WAIT(0); }
        __syncthreads();

        if (i + 2 < NK) {
            int sn = st + 2; if (sn >= 3) sn -= 3;
            uint32_t sb = sbase + sn * STG_B;
            int k0 = (i + 2) * 32;
#pragma unroll
            for (int r = 0; r < 4; r++) {
                CP16(sb + dA[r], pa[r] + k0);
                CP16(sb + dB[r], pb[r] + k0);
            }
            CP_COMMIT();
        }

        uint32_t stA = sbase + st * STG_B;
        uint32_t stB = stA + A_REG;
#pragma unroll
        for (int kg = 0; kg < 2; kg++) {
            uint32_t af[4][4], bfl[16];
#pragma unroll
            for (int mi = 0; mi < 4; mi++)
                LDSM4(af[mi], stA + (uint32_t)(wm * 64 + mi * 16) * ROWB + kg * 32 + a_off);
#pragma unroll
            for (int j = 0; j < 4; j++)
                LDSM4(&bfl[j * 4], stB + (uint32_t)(wn * 64 + j * 16) * ROWB + kg * 32 + b_off);
#pragma unroll
            for (int mi = 0; mi < 4; mi++)
#pragma unroll
                for (int nj = 0; nj < 8; nj++) {
                    int bi = (nj >> 1) * 4 + (nj & 1) * 2;
                    MMA_F16(acc[mi][nj], af[mi], bfl[bi], bfl[bi + 1]);
                }
        }
        st++; if (st >= 3) st -= 3;
    }

    // epilogue: bias + scattered store
#pragma unroll
    for (int mi = 0; mi < 4; mi++) {
        int rl = wm * 64 + mi * 16 + g;
        int cr0 = crow_s[rl];
        int cr1 = crow_s[rl + 8];
#pragma unroll
        for (int nj = 0; nj < 8; nj++) {
            int cb = col0 + wn * 64 + nj * 8 + 2 * t;
            float2 bv = *reinterpret_cast<const float2*>(bias + cb);
            float ox0 = acc[mi][nj][0] + bv.x, oy0 = acc[mi][nj][1] + bv.y;
            float ox1 = acc[mi][nj][2] + bv.x, oy1 = acc[mi][nj][3] + bv.y;
            if (outHalf) {
                __half* C = (__half*)Cbase;
                if (cr0 >= 0)
                    *reinterpret_cast<__half2*>(C + (size_t)cr0 * ldc + cb) = __floats2half2_rn(ox0, oy0);
                if (cr1 >= 0)
                    *reinterpret_cast<__half2*>(C + (size_t)cr1 * ldc + cb) = __floats2half2_rn(ox1, oy1);
            } else {
                float* C = (float*)Cbase;
                if (cr0 >= 0)
                    *reinterpret_cast<float2*>(C + (size_t)cr0 * ldc + cb) = make_float2(ox0, oy0);
                if (cr1 >= 0)
                    *reinterpret_cast<float2*>(C + (size_t)cr1 * ldc + cb) = make_float2(ox1, oy1);
            }
        }
    }
}

// ---------------- fused f32->f16 conversion for x, A, Bw (one launch) ----------------
#define NX4 (T_TOK * D_MODEL / 4)
#define NA4 ((int)((size_t)E_NUM * H_DIM * D_MODEL / 4))
#define NB4 NA4
#define NCVT_BLOCKS ((NX4 + NA4 + NB4) / 256)

__global__ void cvt_all(const float* __restrict__ x,
                        const float* __restrict__ A,
                        const float* __restrict__ Bw)
{
    int idx = blockIdx.x * 256 + threadIdx.x;
    if (blockIdx.x == 0 && threadIdx.x < E_NUM) g_cnt[threadIdx.x] = 0;

    const float4* src;
    uint2* dst;
    int off;
    if (idx < NX4) {
        src = reinterpret_cast<const float4*>(x);
        dst = reinterpret_cast<uint2*>(g_xh);
        off = idx;
    } else if (idx < NX4 + NA4) {
        src = reinterpret_cast<const float4*>(A);
        dst = reinterpret_cast<uint2*>(g_Ah);
        off = idx - NX4;
    } else {
        src = reinterpret_cast<const float4*>(Bw);
        dst = reinterpret_cast<uint2*>(g_Bh);
        off = idx - NX4 - NA4;
    }
    float4 v = src[off];
    __half2 a = __floats2half2_rn(v.x, v.y);
    __half2 b = __floats2half2_rn(v.z, v.w);
    uint2 u;
    u.x = *reinterpret_cast<uint32_t*>(&a);
    u.y = *reinterpret_cast<uint32_t*>(&b);
    dst[off] = u;
}

// ---------------- fp32 SGEMM (proj only; gating must stay fp32-exact) ----------------
// BM=32 for 512-CTA grid (better SM balance). Per-output accumulation remains
// strictly ascending-k FMA order -> bit-identical proj vs previous tiling.
#define PBM 32
#define PBN 64
#define PBK 16

__global__ void __launch_bounds__(128)
sgemm_nt(const float* __restrict__ Abase, int lda,
         const float* __restrict__ B,
         const float* __restrict__ bias,
         float* __restrict__ Cbase, int ldc, int K)
{
    int row0 = blockIdx.y * PBM;
    int col0 = blockIdx.x * PBN;

    __shared__ float As[PBK][36];
    __shared__ float Bs[PBK][68];

    int tid = threadIdx.x;
    float acc[4][4];
#pragma unroll
    for (int i = 0; i < 4; i++)
#pragma unroll
        for (int j = 0; j < 4; j++) acc[i][j] = 0.0f;

    int tr = (tid >> 4) * 4;   // 8 groups * 4 rows = 32 rows
    int tc = (tid & 15) * 4;   // 16 groups * 4 cols = 64 cols

    for (int k0 = 0; k0 < K; k0 += PBK) {
        // A: 32 rows x 16 k = 128 float4, one per thread
        {
            int r  = tid >> 2;
            int kq = (tid & 3) * 4;
            float4 va = *reinterpret_cast<const float4*>(Abase + (size_t)(row0 + r) * lda + k0 + kq);
            As[kq + 0][r] = va.x; As[kq + 1][r] = va.y; As[kq + 2][r] = va.z; As[kq + 3][r] = va.w;
        }
        // B: 64 rows x 16 k = 256 float4, two per thread
#pragma unroll
        for (int l = 0; l < 2; l++) {
            int idx = tid + l * 128;
            int r  = idx >> 2;
            int kq = (idx & 3) * 4;
            float4 vb = *reinterpret_cast<const float4*>(B + (size_t)(col0 + r) * K + k0 + kq);
            Bs[kq + 0][r] = vb.x; Bs[kq + 1][r] = vb.y; Bs[kq + 2][r] = vb.z; Bs[kq + 3][r] = vb.w;
        }
        __syncthreads();
#pragma unroll
        for (int kk = 0; kk < PBK; kk++) {
            float4 a = *reinterpret_cast<const float4*>(&As[kk][tr]);
            float4 b = *reinterpret_cast<const float4*>(&Bs[kk][tc]);
            float av[4] = {a.x, a.y, a.z, a.w};
            float bv[4] = {b.x, b.y, b.z, b.w};
#pragma unroll
            for (int i = 0; i < 4; i++)
#pragma unroll
                for (int j = 0; j < 4; j++) acc[i][j] += av[i] * bv[j];
        }
        __syncthreads();
    }

    float bvals[4];
#pragma unroll
    for (int j = 0; j < 4; j++) bvals[j] = bias[col0 + tc + j];
#pragma unroll
    for (int i = 0; i < 4; i++) {
        float4 o;
        o.x = acc[i][0] + bvals[0];
        o.y = acc[i][1] + bvals[1];
        o.z = acc[i][2] + bvals[2];
        o.w = acc[i][3] + bvals[3];
        *reinterpret_cast<float4*>(Cbase + (size_t)(row0 + tr + i) * ldc + col0 + tc) = o;
    }
}

// ---------------- gating (computes simn/scale locally) ----------------
__device__ __forceinline__ float warp_sum(float v) {
#pragma unroll
    for (int o = 16; o > 0; o >>= 1) v += __shfl_xor_sync(0xffffffffu, v, o);
    return v;
}

__global__ void gate_kernel(const float* __restrict__ sim, const float* __restrict__ temp) {
    __shared__ float red[E_NUM][P_DIM];
    __shared__ float s_simn[P_DIM * E_NUM];
    int tid = threadIdx.x;  // 256 = P_DIM

    {
        int p = tid;
        float s[E_NUM];
#pragma unroll
        for (int e = 0; e < E_NUM; e++) {
            s[e] = sim[p * E_NUM + e];
            red[e][p] = s[e] * s[e];
        }
        __syncthreads();
        for (int off = 128; off > 0; off >>= 1) {
            if (p < off)
#pragma unroll
                for (int e = 0; e < E_NUM; e++) red[e][p] += red[e][p + off];
            __syncthreads();
        }
#pragma unroll
        for (int e = 0; e < E_NUM; e++) {
            float inv = 1.0f / fmaxf(sqrtf(red[e][0]), 1e-12f);
            s_simn[p * E_NUM + e] = s[e] * inv;
        }
    }
    __syncthreads();
    float scale = expf(fminf(temp[0], CLAMP_MAX));

    int warp = tid >> 5, lane = tid & 31;
    int t = blockIdx.x * 8 + warp;

    float v[8];
#pragma unroll
    for (int j = 0; j < 8; j++) v[j] = g_proj[t * P_DIM + lane + 32 * j];

    float ss = 0.0f;
#pragma unroll
    for (int j = 0; j < 8; j++) ss += v[j] * v[j];
    ss = warp_sum(ss);
    float inv = 1.0f / fmaxf(sqrtf(ss), 1e-12f);

    float l[E_NUM];
#pragma unroll
    for (int e = 0; e < E_NUM; e++) {
        float d = 0.0f;
#pragma unroll
        for (int j = 0; j < 8; j++) d += v[j] * s_simn[(lane + 32 * j) * E_NUM + e];
        l[e] = warp_sum(d);
    }

    if (lane == 0) {
        float m = -1e30f;
#pragma unroll
        for (int e = 0; e < E_NUM; e++) { l[e] = l[e] * inv * scale; m = fmaxf(m, l[e]); }
        float p[E_NUM], s = 0.0f;
#pragma unroll
        for (int e = 0; e < E_NUM; e++) { p[e] = expf(l[e] - m); s += p[e]; }
        float rs = 1.0f / s;
#pragma unroll
        for (int e = 0; e < E_NUM; e++) { p[e] *= rs; g_probs[t * E_NUM + e] = p[e]; }

        float v1 = -1.0f; int i1 = 0;
#pragma unroll
        for (int e = 0; e < E_NUM; e++) if (p[e] > v1) { v1 = p[e]; i1 = e; }
        float v2 = -1.0f; int i2 = 0;
#pragma unroll
        for (int e = 0; e < E_NUM; e++) if (e != i1 && p[e] > v2) { v2 = p[e]; i2 = e; }

        float denom = v1 + v2 + 1e-8f;
        float w1 = v1 / denom, w2 = v2 / denom;

        int s1 = atomicAdd(&g_cnt[i1], 1);
        g_tok[i1 * T_TOK + s1]    = t;
        g_pairid[i1 * T_TOK + s1] = 2 * t;
        g_pw[2 * t] = w1;
        int s2 = atomicAdd(&g_cnt[i2], 1);
        g_tok[i2 * T_TOK + s2]    = t;
        g_pairid[i2 * T_TOK + s2] = 2 * t + 1;
        g_pw[2 * t + 1] = w2;
    }
}

// ---------------- combine ----------------
__global__ void combine_kernel(const float* __restrict__ x, float* __restrict__ out) {
    int idx = blockIdx.x * 256 + threadIdx.x;
    int t  = idx >> 8;
    int c4 = idx & 255;
    float w0 = g_pw[2 * t], w1 = g_pw[2 * t + 1];
    float ws = w0 + w1;
    const float4* x4 = reinterpret_cast<const float4*>(x);
    const float4* f4 = reinterpret_cast<const float4*>(g_f);
    float4 xv = x4[idx];
    float4 f0 = f4[(size_t)(2 * t) * 256 + c4];
    float4 f1 = f4[(size_t)(2 * t + 1) * 256 + c4];
    float4 o;
    o.x = ws * xv.x + w0 * f0.x + w1 * f1.x;
    o.y = ws * xv.y + w0 * f0.y + w1 * f1.y;
    o.z = ws * xv.z + w0 * f0.z + w1 * f1.z;
    o.w = ws * xv.w + w0 * f0.w + w1 * f1.w;
    reinterpret_cast<float4*>(out)[idx] = o;
}

// ---------------- finalize (1024 threads; same per-expert reduction order) ----------------
__global__ void finalize_kernel(float* __restrict__ out) {
    __shared__ float red[1024];
    __shared__ float fr[E_NUM];
    int tid = threadIdx.x;  // 1024
    float part[E_NUM];
#pragma unroll
    for (int e = 0; e < E_NUM; e++) part[e] = 0.0f;
    for (int t = tid; t < T_TOK; t += 1024)
#pragma unroll
        for (int e = 0; e < E_NUM; e++) part[e] += g_probs[t * E_NUM + e];

    for (int e = 0; e < E_NUM; e++) {
        red[tid] = part[e];
        __syncthreads();
        for (int off = 512; off > 0; off >>= 1) {
            if (tid < off) red[tid] += red[tid + off];
            __syncthreads();
        }
        if (tid == 0) fr[e] = red[0] / (float)T_TOK;
        __syncthreads();
    }
    if (tid == 0) {
        float aux = 0.0f;
#pragma unroll
        for (int e = 0; e < E_NUM; e++) {
            float d = fr[e] - 1.0f / (float)E_NUM;
            aux += d * d;
        }
        out[OUT_MAIN] = aux;
#pragma unroll
        for (int e = 0; e < E_NUM; e++) out[OUT_MAIN + 1 + e] = fr[e];
#pragma unroll
        for (int e = 0; e < E_NUM; e++) out[OUT_MAIN + 9 + e] = (float)g_cnt[e];
    }
}

// ---------------- launch (strict serial) ----------------
extern "C" void kernel_launch(void* const* d_in, const int* in_sizes, int n_in,
                              void* d_out, int out_size) {
    const float* x    = (const float*)d_in[0];
    const float* Wp   = (const float*)d_in[1];
    const float* bp   = (const float*)d_in[2];
    const float* sim  = (const float*)d_in[3];
    const float* temp = (const float*)d_in[4];
    const float* A    = (const float*)d_in[5];
    const float* ab   = (const float*)d_in[6];
    const float* Bw   = (const float*)d_in[7];
    const float* bb   = (const float*)d_in[8];
    float* out = (float*)d_out;

    float *p_proj, *p_f;
    __half *p_xh, *p_Ah, *p_Bh, *p_h;
    int *p_tok, *p_pair, *p_cnt;
    cudaGetSymbolAddress((void**)&p_proj, g_proj);
    cudaGetSymbolAddress((void**)&p_xh,   g_xh);
    cudaGetSymbolAddress((void**)&p_Ah,   g_Ah);
    cudaGetSymbolAddress((void**)&p_Bh,   g_Bh);
    cudaGetSymbolAddress((void**)&p_h,    g_h);
    cudaGetSymbolAddress((void**)&p_f,    g_f);
    cudaGetSymbolAddress((void**)&p_tok,  g_tok);
    cudaGetSymbolAddress((void**)&p_pair, g_pairid);
    cudaGetSymbolAddress((void**)&p_cnt,  g_cnt);

    cudaFuncSetAttribute(hgemm, cudaFuncAttributeMaxDynamicSharedMemorySize, SMEM_DYN);

    // 0) fused fp16 conversions (x, A, Bw) + counter zeroing — one launch
    cvt_all<<<NCVT_BLOCKS, 256>>>(x, A, Bw);

    // 1) proj = X @ Wp^T + bp  (fp32 exact — 512-CTA grid for SM balance)
    sgemm_nt<<<dim3(P_DIM / PBN, T_TOK / PBM, 1), 128>>>(
        x, D_MODEL, Wp, bp, p_proj, P_DIM, D_MODEL);

    // 2) gating + routing
    gate_kernel<<<T_TOK / 8, 256>>>(sim, temp);

    // 3) h = gather(xh) @ Ah_e^T + a_bias   (fp16 mma, fp16 out)
    hgemm<<<dim3(T_TOK / MBM, H_DIM / MBN, E_NUM), 128, SMEM_DYN>>>(
        p_xh, D_MODEL, p_tok,
        p_Ah, (size_t)H_DIM * D_MODEL, ab, H_DIM,
        p_h, H_DIM, p_pair,
        p_cnt, D_MODEL, 1);

    // 4) f = gather(h) @ Bh_e^T + b_bias    (fp16 mma, fp32 out)
    hgemm<<<dim3(T_TOK / MBM, D_MODEL / MBN, E_NUM), 128, SMEM_DYN>>>(
        p_h, H_DIM, p_pair,
        p_Bh, (size_t)D_MODEL * H_DIM, bb, D_MODEL,
        p_f, D_MODEL, p_pair,
        p_cnt, H_DIM, 0);

    // 5) combine
    combine_kernel<<<(T_TOK * D_MODEL / 4) / 256, 256>>>(x, out);

    // 6) aux outputs
    finalize_kernel<<<1, 1024>>>(out);
}

// round 17
// speedup vs baseline: 1.2661x; 1.0202x over previous
#include <cuda_runtime.h>
#include <cuda_fp16.h>
#include <cstdint>

#define T_TOK   4096
#define D_MODEL 1024
#define E_NUM   8
#define H_DIM   4096
#define P_DIM   256
#define NPAIR   (T_TOK * 2)
#define OUT_MAIN (T_TOK * D_MODEL)
#define CLAMP_MAX 4.605170185988091f

// ---------------- scratch (static device memory; no allocations) ----------------
__device__ __align__(16) float  g_proj[T_TOK * P_DIM];
__device__ __align__(16) __half g_xh[T_TOK * D_MODEL];
__device__ __align__(16) __half g_Ah[(size_t)E_NUM * H_DIM * D_MODEL];
__device__ __align__(16) __half g_Bh[(size_t)E_NUM * D_MODEL * H_DIM];
__device__ __align__(16) __half g_h[(size_t)NPAIR * H_DIM];
__device__ __align__(16) float  g_f[(size_t)NPAIR * D_MODEL];
__device__ __align__(16) float  g_probs[T_TOK * E_NUM];
__device__ int   g_cnt[E_NUM];
__device__ int   g_tok[E_NUM * T_TOK];
__device__ int   g_pairid[E_NUM * T_TOK];
__device__ float g_pw[NPAIR];

// ================= helpers =================
__device__ __forceinline__ uint32_t smem_u32(const void* p) {
    uint32_t a;
    asm("{ .reg .u64 t; cvta.to.shared.u64 t, %1; cvt.u32.u64 %0, t; }" : "=r"(a) : "l"(p));
    return a;
}
#define CP16(sm, gm) \
    asm volatile("{ .reg .u64 gp; cvta.to.global.u64 gp, %1; " \
                 "cp.async.cg.shared.global [%0], [gp], 16; }" \
                 :: "r"(sm), "l"(gm) : "memory")
#define CP_COMMIT()  asm volatile("cp.async.commit_group;" ::: "memory")
#define CP_WAIT(n)   asm volatile("cp.async.wait_group %0;" :: "n"(n) : "memory")

#define LDSM4(r, addr) \
    asm volatile("ldmatrix.sync.aligned.m8n8.x4.shared.b16 {%0,%1,%2,%3}, [%4];" \
        : "=r"((r)[0]), "=r"((r)[1]), "=r"((r)[2]), "=r"((r)[3]) : "r"(addr))

#define MMA_F16(c, a, b0, b1) \
    asm volatile("mma.sync.aligned.m16n8k16.row.col.f32.f16.f16.f32 " \
        "{%0,%1,%2,%3}, {%4,%5,%6,%7}, {%8,%9}, {%0,%1,%2,%3};" \
        : "+f"((c)[0]), "+f"((c)[1]), "+f"((c)[2]), "+f"((c)[3]) \
        : "r"((a)[0]), "r"((a)[1]), "r"((a)[2]), "r"((a)[3]), \
          "r"(b0), "r"(b1))

// ================= fp16 mma.sync grouped NT GEMM (R11 config — final) =================
#define MBM 128
#define MBN 128
#define ROWB 80
#define A_REG (MBM * ROWB)
#define STG_B (2 * A_REG)
#define SMEM_DYN (3 * STG_B)

__global__ void __launch_bounds__(128, 2)
hgemm(const __half* __restrict__ Abase, int lda,
      const int* __restrict__ gather,
      const __half* __restrict__ Bbase, size_t bstride,
      const float* __restrict__ biasbase, int biasstride,
      void* __restrict__ Cbase, int ldc,
      const int* __restrict__ crow,
      const int* __restrict__ cntArr, int K, int outHalf)
{
    int z = blockIdx.z;
    int M = cntArr[z];
    int row0 = blockIdx.x * MBM;
    if (row0 >= M) return;
    int col0 = blockIdx.y * MBN;
    const __half* Bexp = Bbase + (size_t)z * bstride;
    const float* bias = biasbase + (size_t)z * biasstride;
    const int* gat = gather + z * T_TOK;
    const int* crs = crow + z * T_TOK;

    __shared__ int arow_s[MBM];
    __shared__ int crow_s[MBM];
    extern __shared__ char ds[];
    uint32_t sbase = smem_u32(ds);

    int tid  = threadIdx.x;
    int warp = tid >> 5, lane = tid & 31;
    int g = lane >> 2, t = lane & 3;
    int wm = warp >> 1;
    int wn = warp & 1;

    {
        int r = row0 + tid;
        int rc = min(r, M - 1);
        arow_s[tid] = gat[rc];
        crow_s[tid] = (r < M) ? crs[r] : -1;
    }
    __syncthreads();

    int frow = tid >> 2;
    int ch   = tid & 3;
    const __half* pa[4];
    const __half* pb[4];
    uint32_t dA[4], dB[4];
#pragma unroll
    for (int r = 0; r < 4; r++) {
        int rowr = frow + r * 32;
        pa[r] = Abase + (size_t)arow_s[rowr] * lda + ch * 8;
        pb[r] = Bexp + (size_t)(col0 + rowr) * K + ch * 8;
        dA[r] = (uint32_t)rowr * ROWB + ch * 16;
        dB[r] = dA[r] + A_REG;
    }

    uint32_t a_off = (uint32_t)((lane & 7) + ((lane >> 3) & 1) * 8) * ROWB + (lane >> 4) * 16;
    uint32_t b_off = (uint32_t)((lane & 7) + ((lane >> 4) & 1) * 8) * ROWB + ((lane >> 3) & 1) * 16;

    int NK = K >> 5;

#pragma unroll
    for (int s = 0; s < 2; s++) {
        uint32_t sb = sbase + s * STG_B;
        int k0 = s * 32;
#pragma unroll
        for (int r = 0; r < 4; r++) {
            CP16(sb + dA[r], pa[r] + k0);
            CP16(sb + dB[r], pb[r] + k0);
        }
        CP_COMMIT();
    }

    float acc[4][8][4];
#pragma unroll
    for (int mi = 0; mi < 4; mi++)
#pragma unroll
        for (int nj = 0; nj < 8; nj++)
#pragma unroll
            for (int q = 0; q < 4; q++) acc[mi][nj][q] = 0.0f;

    int st = 0;
    for (int i = 0; i < NK; i++) {
        if (i + 1 < NK) { CP_WAIT(1); } else { CP_WAIT(0); }
        __syncthreads();

        if (i + 2 < NK) {
            int sn = st + 2; if (sn >= 3) sn -= 3;
            uint32_t sb = sbase + sn * STG_B;
            int k0 = (i + 2) * 32;
#pragma unroll
            for (int r = 0; r < 4; r++) {
                CP16(sb + dA[r], pa[r] + k0);
                CP16(sb + dB[r], pb[r] + k0);
            }
            CP_COMMIT();
        }

        uint32_t stA = sbase + st * STG_B;
        uint32_t stB = stA + A_REG;
#pragma unroll
        for (int kg = 0; kg < 2; kg++) {
            uint32_t af[4][4], bfl[16];
#pragma unroll
            for (int mi = 0; mi < 4; mi++)
                LDSM4(af[mi], stA + (uint32_t)(wm * 64 + mi * 16) * ROWB + kg * 32 + a_off);
#pragma unroll
            for (int j = 0; j < 4; j++)
                LDSM4(&bfl[j * 4], stB + (uint32_t)(wn * 64 + j * 16) * ROWB + kg * 32 + b_off);
#pragma unroll
            for (int mi = 0; mi < 4; mi++)
#pragma unroll
                for (int nj = 0; nj < 8; nj++) {
                    int bi = (nj >> 1) * 4 + (nj & 1) * 2;
                    MMA_F16(acc[mi][nj], af[mi], bfl[bi], bfl[bi + 1]);
                }
        }
        st++; if (st >= 3) st -= 3;
    }

    // epilogue: bias + scattered store
#pragma unroll
    for (int mi = 0; mi < 4; mi++) {
        int rl = wm * 64 + mi * 16 + g;
        int cr0 = crow_s[rl];
        int cr1 = crow_s[rl + 8];
#pragma unroll
        for (int nj = 0; nj < 8; nj++) {
            int cb = col0 + wn * 64 + nj * 8 + 2 * t;
            float2 bv = *reinterpret_cast<const float2*>(bias + cb);
            float ox0 = acc[mi][nj][0] + bv.x, oy0 = acc[mi][nj][1] + bv.y;
            float ox1 = acc[mi][nj][2] + bv.x, oy1 = acc[mi][nj][3] + bv.y;
            if (outHalf) {
                __half* C = (__half*)Cbase;
                if (cr0 >= 0)
                    *reinterpret_cast<__half2*>(C + (size_t)cr0 * ldc + cb) = __floats2half2_rn(ox0, oy0);
                if (cr1 >= 0)
                    *reinterpret_cast<__half2*>(C + (size_t)cr1 * ldc + cb) = __floats2half2_rn(ox1, oy1);
            } else {
                float* C = (float*)Cbase;
                if (cr0 >= 0)
                    *reinterpret_cast<float2*>(C + (size_t)cr0 * ldc + cb) = make_float2(ox0, oy0);
                if (cr1 >= 0)
                    *reinterpret_cast<float2*>(C + (size_t)cr1 * ldc + cb) = make_float2(ox1, oy1);
            }
        }
    }
}

// ---------------- fused f32->f16 conversion for x, A, Bw (one launch, 2 elems/thread) ----------------
#define NX4 (T_TOK * D_MODEL / 4)                          // 1,048,576 (512-aligned)
#define NA4 ((int)((size_t)E_NUM * H_DIM * D_MODEL / 4))   // 8,388,608 (512-aligned)
#define NB4 NA4
#define NCVT_TOTAL (NX4 + NA4 + NB4)
#define NCVT_BLOCKS (NCVT_TOTAL / 512)

__device__ __forceinline__ void cvt_one(int idx,
                                        const float* __restrict__ x,
                                        const float* __restrict__ A,
                                        const float* __restrict__ Bw)
{
    const float4* src;
    uint2* dst;
    int off;
    if (idx < NX4) {
        src = reinterpret_cast<const float4*>(x);
        dst = reinterpret_cast<uint2*>(g_xh);
        off = idx;
    } else if (idx < NX4 + NA4) {
        src = reinterpret_cast<const float4*>(A);
        dst = reinterpret_cast<uint2*>(g_Ah);
        off = idx - NX4;
    } else {
        src = reinterpret_cast<const float4*>(Bw);
        dst = reinterpret_cast<uint2*>(g_Bh);
        off = idx - NX4 - NA4;
    }
    float4 v = src[off];
    __half2 a = __floats2half2_rn(v.x, v.y);
    __half2 b = __floats2half2_rn(v.z, v.w);
    uint2 u;
    u.x = *reinterpret_cast<uint32_t*>(&a);
    u.y = *reinterpret_cast<uint32_t*>(&b);
    dst[off] = u;
}

__global__ void cvt_all(const float* __restrict__ x,
                        const float* __restrict__ A,
                        const float* __restrict__ Bw)
{
    if (blockIdx.x == 0 && threadIdx.x < E_NUM) g_cnt[threadIdx.x] = 0;
    int base = blockIdx.x * 512 + threadIdx.x;
    cvt_one(base,       x, A, Bw);
    cvt_one(base + 256, x, A, Bw);
}

// ---------------- fp32 SGEMM (proj only; gating must stay fp32-exact) ----------------
#define PBM 32
#define PBN 64
#define PBK 16

__global__ void __launch_bounds__(128)
sgemm_nt(const float* __restrict__ Abase, int lda,
         const float* __restrict__ B,
         const float* __restrict__ bias,
         float* __restrict__ Cbase, int ldc, int K)
{
    int row0 = blockIdx.y * PBM;
    int col0 = blockIdx.x * PBN;

    __shared__ float As[PBK][36];
    __shared__ float Bs[PBK][68];

    int tid = threadIdx.x;
    float acc[4][4];
#pragma unroll
    for (int i = 0; i < 4; i++)
#pragma unroll
        for (int j = 0; j < 4; j++) acc[i][j] = 0.0f;

    int tr = (tid >> 4) * 4;
    int tc = (tid & 15) * 4;

    for (int k0 = 0; k0 < K; k0 += PBK) {
        {
            int r  = tid >> 2;
            int kq = (tid & 3) * 4;
            float4 va = *reinterpret_cast<const float4*>(Abase + (size_t)(row0 + r) * lda + k0 + kq);
            As[kq + 0][r] = va.x; As[kq + 1][r] = va.y; As[kq + 2][r] = va.z; As[kq + 3][r] = va.w;
        }
#pragma unroll
        for (int l = 0; l < 2; l++) {
            int idx = tid + l * 128;
            int r  = idx >> 2;
            int kq = (idx & 3) * 4;
            float4 vb = *reinterpret_cast<const float4*>(B + (size_t)(col0 + r) * K + k0 + kq);
            Bs[kq + 0][r] = vb.x; Bs[kq + 1][r] = vb.y; Bs[kq + 2][r] = vb.z; Bs[kq + 3][r] = vb.w;
        }
        __syncthreads();
#pragma unroll
        for (int kk = 0; kk < PBK; kk++) {
            float4 a = *reinterpret_cast<const float4*>(&As[kk][tr]);
            float4 b = *reinterpret_cast<const float4*>(&Bs[kk][tc]);
            float av[4] = {a.x, a.y, a.z, a.w};
            float bv[4] = {b.x, b.y, b.z, b.w};
#pragma unroll
            for (int i = 0; i < 4; i++)
#pragma unroll
                for (int j = 0; j < 4; j++) acc[i][j] += av[i] * bv[j];
        }
        __syncthreads();
    }

    float bvals[4];
#pragma unroll
    for (int j = 0; j < 4; j++) bvals[j] = bias[col0 + tc + j];
#pragma unroll
    for (int i = 0; i < 4; i++) {
        float4 o;
        o.x = acc[i][0] + bvals[0];
        o.y = acc[i][1] + bvals[1];
        o.z = acc[i][2] + bvals[2];
        o.w = acc[i][3] + bvals[3];
        *reinterpret_cast<float4*>(Cbase + (size_t)(row0 + tr + i) * ldc + col0 + tc) = o;
    }
}

// ---------------- gating (computes simn/scale locally) ----------------
__device__ __forceinline__ float warp_sum(float v) {
#pragma unroll
    for (int o = 16; o > 0; o >>= 1) v += __shfl_xor_sync(0xffffffffu, v, o);
    return v;
}

__global__ void gate_kernel(const float* __restrict__ sim, const float* __restrict__ temp) {
    __shared__ float red[E_NUM][P_DIM];
    __shared__ float s_simn[P_DIM * E_NUM];
    int tid = threadIdx.x;  // 256 = P_DIM

    {
        int p = tid;
        float s[E_NUM];
#pragma unroll
        for (int e = 0; e < E_NUM; e++) {
            s[e] = sim[p * E_NUM + e];
            red[e][p] = s[e] * s[e];
        }
        __syncthreads();
        for (int off = 128; off > 0; off >>= 1) {
            if (p < off)
#pragma unroll
                for (int e = 0; e < E_NUM; e++) red[e][p] += red[e][p + off];
            __syncthreads();
        }
#pragma unroll
        for (int e = 0; e < E_NUM; e++) {
            float inv = 1.0f / fmaxf(sqrtf(red[e][0]), 1e-12f);
            s_simn[p * E_NUM + e] = s[e] * inv;
        }
    }
    __syncthreads();
    float scale = expf(fminf(temp[0], CLAMP_MAX));

    int warp = tid >> 5, lane = tid & 31;
    int t = blockIdx.x * 8 + warp;

    float v[8];
#pragma unroll
    for (int j = 0; j < 8; j++) v[j] = g_proj[t * P_DIM + lane + 32 * j];

    float ss = 0.0f;
#pragma unroll
    for (int j = 0; j < 8; j++) ss += v[j] * v[j];
    ss = warp_sum(ss);
    float inv = 1.0f / fmaxf(sqrtf(ss), 1e-12f);

    float l[E_NUM];
#pragma unroll
    for (int e = 0; e < E_NUM; e++) {
        float d = 0.0f;
#pragma unroll
        for (int j = 0; j < 8; j++) d += v[j] * s_simn[(lane + 32 * j) * E_NUM + e];
        l[e] = warp_sum(d);
    }

    if (lane == 0) {
        float m = -1e30f;
#pragma unroll
        for (int e = 0; e < E_NUM; e++) { l[e] = l[e] * inv * scale; m = fmaxf(m, l[e]); }
        float p[E_NUM], s = 0.0f;
#pragma unroll
        for (int e = 0; e < E_NUM; e++) { p[e] = expf(l[e] - m); s += p[e]; }
        float rs = 1.0f / s;
#pragma unroll
        for (int e = 0; e < E_NUM; e++) { p[e] *= rs; g_probs[t * E_NUM + e] = p[e]; }

        float v1 = -1.0f; int i1 = 0;
#pragma unroll
        for (int e = 0; e < E_NUM; e++) if (p[e] > v1) { v1 = p[e]; i1 = e; }
        float v2 = -1.0f; int i2 = 0;
#pragma unroll
        for (int e = 0; e < E_NUM; e++) if (e != i1 && p[e] > v2) { v2 = p[e]; i2 = e; }

        float denom = v1 + v2 + 1e-8f;
        float w1 = v1 / denom, w2 = v2 / denom;

        int s1 = atomicAdd(&g_cnt[i1], 1);
        g_tok[i1 * T_TOK + s1]    = t;
        g_pairid[i1 * T_TOK + s1] = 2 * t;
        g_pw[2 * t] = w1;
        int s2 = atomicAdd(&g_cnt[i2], 1);
        g_tok[i2 * T_TOK + s2]    = t;
        g_pairid[i2 * T_TOK + s2] = 2 * t + 1;
        g_pw[2 * t + 1] = w2;
    }
}

// ---------------- combine ----------------
__global__ void combine_kernel(const float* __restrict__ x, float* __restrict__ out) {
    int idx = blockIdx.x * 256 + threadIdx.x;
    int t  = idx >> 8;
    int c4 = idx & 255;
    float w0 = g_pw[2 * t], w1 = g_pw[2 * t + 1];
    float ws = w0 + w1;
    const float4* x4 = reinterpret_cast<const float4*>(x);
    const float4* f4 = reinterpret_cast<const float4*>(g_f);
    float4 xv = x4[idx];
    float4 f0 = f4[(size_t)(2 * t) * 256 + c4];
    float4 f1 = f4[(size_t)(2 * t + 1) * 256 + c4];
    float4 o;
    o.x = ws * xv.x + w0 * f0.x + w1 * f1.x;
    o.y = ws * xv.y + w0 * f0.y + w1 * f1.y;
    o.z = ws * xv.z + w0 * f0.z + w1 * f1.z;
    o.w = ws * xv.w + w0 * f0.w + w1 * f1.w;
    reinterpret_cast<float4*>(out)[idx] = o;
}

// ---------------- finalize (1024 threads; same per-expert reduction order) ----------------
__global__ void finalize_kernel(float* __restrict__ out) {
    __shared__ float red[1024];
    __shared__ float fr[E_NUM];
    int tid = threadIdx.x;  // 1024
    float part[E_NUM];
#pragma unroll
    for (int e = 0; e < E_NUM; e++) part[e] = 0.0f;
    for (int t = tid; t < T_TOK; t += 1024)
#pragma unroll
        for (int e = 0; e < E_NUM; e++) part[e] += g_probs[t * E_NUM + e];

    for (int e = 0; e < E_NUM; e++) {
        red[tid] = part[e];
        __syncthreads();
        for (int off = 512; off > 0; off >>= 1) {
            if (tid < off) red[tid] += red[tid + off];
            __syncthreads();
        }
        if (tid == 0) fr[e] = red[0] / (float)T_TOK;
        __syncthreads();
    }
    if (tid == 0) {
        float aux = 0.0f;
#pragma unroll
        for (int e = 0; e < E_NUM; e++) {
            float d = fr[e] - 1.0f / (float)E_NUM;
            aux += d * d;
        }
        out[OUT_MAIN] = aux;
#pragma unroll
        for (int e = 0; e < E_NUM; e++) out[OUT_MAIN + 1 + e] = fr[e];
#pragma unroll
        for (int e = 0; e < E_NUM; e++) out[OUT_MAIN + 9 + e] = (float)g_cnt[e];
    }
}

// ---------------- launch (strict serial) ----------------
extern "C" void kernel_launch(void* const* d_in, const int* in_sizes, int n_in,
                              void* d_out, int out_size) {
    const float* x    = (const float*)d_in[0];
    const float* Wp   = (const float*)d_in[1];
    const float* bp   = (const float*)d_in[2];
    const float* sim  = (const float*)d_in[3];
    const float* temp = (const float*)d_in[4];
    const float* A    = (const float*)d_in[5];
    const float* ab   = (const float*)d_in[6];
    const float* Bw   = (const float*)d_in[7];
    const float* bb   = (const float*)d_in[8];
    float* out = (float*)d_out;

    float *p_proj, *p_f;
    __half *p_xh, *p_Ah, *p_Bh, *p_h;
    int *p_tok, *p_pair, *p_cnt;
    cudaGetSymbolAddress((void**)&p_proj, g_proj);
    cudaGetSymbolAddress((void**)&p_xh,   g_xh);
    cudaGetSymbolAddress((void**)&p_Ah,   g_Ah);
    cudaGetSymbolAddress((void**)&p_Bh,   g_Bh);
    cudaGetSymbolAddress((void**)&p_h,    g_h);
    cudaGetSymbolAddress((void**)&p_f,    g_f);
    cudaGetSymbolAddress((void**)&p_tok,  g_tok);
    cudaGetSymbolAddress((void**)&p_pair, g_pairid);
    cudaGetSymbolAddress((void**)&p_cnt,  g_cnt);

    cudaFuncSetAttribute(hgemm, cudaFuncAttributeMaxDynamicSharedMemorySize, SMEM_DYN);

    // 0) fused fp16 conversions (x, A, Bw) + counter zeroing — one launch, 2 elems/thread
    cvt_all<<<NCVT_BLOCKS, 256>>>(x, A, Bw);

    // 1) proj = X @ Wp^T + bp  (fp32 exact — 512-CTA grid for SM balance)
    sgemm_nt<<<dim3(P_DIM / PBN, T_TOK / PBM, 1), 128>>>(
        x, D_MODEL, Wp, bp, p_proj, P_DIM, D_MODEL);

    // 2) gating + routing
    gate_kernel<<<T_TOK / 8, 256>>>(sim, temp);

    // 3) h = gather(xh) @ Ah_e^T + a_bias   (fp16 mma, fp16 out)
    hgemm<<<dim3(T_TOK / MBM, H_DIM / MBN, E_NUM), 128, SMEM_DYN>>>(
        p_xh, D_MODEL, p_tok,
        p_Ah, (size_t)H_DIM * D_MODEL, ab, H_DIM,
        p_h, H_DIM, p_pair,
        p_cnt, D_MODEL, 1);

    // 4) f = gather(h) @ Bh_e^T + b_bias    (fp16 mma, fp32 out)
    hgemm<<<dim3(T_TOK / MBM, D_MODEL / MBN, E_NUM), 128, SMEM_DYN>>>(
        p_h, H_DIM, p_pair,
        p_Bh, (size_t)D_MODEL * H_DIM, bb, D_MODEL,
        p_f, D_MODEL, p_pair,
        p_cnt, H_DIM, 0);

    // 5) combine
    combine_kernel<<<(T_TOK * D_MODEL / 4) / 256, 256>>>(x, out);

    // 6) aux outputs
    finalize_kernel<<<1, 1024>>>(out);
}